// round 2
// baseline (speedup 1.0000x reference)
#include <cuda_runtime.h>

#define BB 2
#define LL 2048
#define DM 1024
#define NH 16
#define DKV 64
#define NEGV (-10000.0f)
#define TQ 128
#define TK 64
#define AST 68

// Scratch (device globals: allocation-free per harness rules)
__device__ float g_Qh[(size_t)BB * NH * LL * DKV];
__device__ float g_Kh[(size_t)BB * NH * LL * DKV];
__device__ float g_Vh[(size_t)BB * NH * LL * DKV];
__device__ float g_BM[(size_t)BB * LL * LL];
__device__ float g_O[(size_t)BB * LL * DM];

__device__ __forceinline__ unsigned f2tf(float f) {
    unsigned u;
    asm("cvt.rna.tf32.f32 %0, %1;" : "=r"(u) : "f"(f));
    return u;
}

__device__ __forceinline__ void mma8(float* c, unsigned a0, unsigned a1,
                                     unsigned a2, unsigned a3,
                                     unsigned b0, unsigned b1) {
    asm volatile(
        "mma.sync.aligned.m16n8k8.row.col.f32.tf32.tf32.f32 "
        "{%0,%1,%2,%3},{%4,%5,%6,%7},{%8,%9},{%0,%1,%2,%3};"
        : "+f"(c[0]), "+f"(c[1]), "+f"(c[2]), "+f"(c[3])
        : "r"(a0), "r"(a1), "r"(a2), "r"(a3), "r"(b0), "r"(b1));
}

// ---------------------------------------------------------------------------
// Kernel 1: fuse mask+bias into one fp32 tensor.
// masked (mask==0) -> exactly -10000; else bias value.
// ---------------------------------------------------------------------------
__global__ void fuse_bm_kernel(const int4* __restrict__ mask,
                               const float4* __restrict__ bias,
                               float4* __restrict__ bm) {
    int i = blockIdx.x * blockDim.x + threadIdx.x;
    int4 m = mask[i];
    float4 bv = bias[i];
    float4 r;
    r.x = m.x ? bv.x : NEGV;
    r.y = m.y ? bv.y : NEGV;
    r.z = m.z ? bv.z : NEGV;
    r.w = m.w ? bv.w : NEGV;
    bm[i] = r;
}

// ---------------------------------------------------------------------------
// Kernel 2: TF32 tiled GEMM, C[M,N] = A[M,K] @ B[K,N] * scale.
// BM=BN=128, BK=32, 8 warps (2x4), warp tile 64x32 via m16n8k8.
// HSPLIT: write C to head-split layout [b][h][l][64] instead of row-major.
// ---------------------------------------------------------------------------
template <bool HSPLIT>
__global__ __launch_bounds__(256) void gemm_tf32(const float* __restrict__ A,
                                                 const float* __restrict__ B,
                                                 float* __restrict__ C,
                                                 int M, int N, int K,
                                                 float scale) {
    __shared__ unsigned As[128][36];   // padded: conflict-free frag loads
    __shared__ unsigned Bs[32][136];
    const int tid = threadIdx.x, lane = tid & 31, wid = tid >> 5;
    const int g = lane >> 2, t4 = lane & 3;
    const int wm = wid >> 2, wn = wid & 3;
    const int row0 = blockIdx.y * 128, col0 = blockIdx.x * 128;

    float acc[4][4][4];
#pragma unroll
    for (int m = 0; m < 4; m++)
#pragma unroll
        for (int n = 0; n < 4; n++)
#pragma unroll
            for (int i = 0; i < 4; i++) acc[m][n][i] = 0.f;

    for (int kt = 0; kt < K; kt += 32) {
#pragma unroll
        for (int i = 0; i < 4; i++) {
            int f = tid + i * 256;
            int r = f >> 3, c4 = (f & 7) * 4;
            float4 v = *(const float4*)(A + (size_t)(row0 + r) * K + kt + c4);
            uint4 u = {f2tf(v.x), f2tf(v.y), f2tf(v.z), f2tf(v.w)};
            *(uint4*)&As[r][c4] = u;
        }
#pragma unroll
        for (int i = 0; i < 4; i++) {
            int f = tid + i * 256;
            int r = f >> 5, c4 = (f & 31) * 4;
            float4 v = *(const float4*)(B + (size_t)(kt + r) * N + col0 + c4);
            uint4 u = {f2tf(v.x), f2tf(v.y), f2tf(v.z), f2tf(v.w)};
            *(uint4*)&Bs[r][c4] = u;
        }
        __syncthreads();
#pragma unroll
        for (int ks = 0; ks < 4; ks++) {
            unsigned af[4][4], bf[4][2];
#pragma unroll
            for (int m = 0; m < 4; m++) {
                int r = wm * 64 + m * 16 + g, c = ks * 8 + t4;
                af[m][0] = As[r][c];
                af[m][1] = As[r + 8][c];
                af[m][2] = As[r][c + 4];
                af[m][3] = As[r + 8][c + 4];
            }
#pragma unroll
            for (int n = 0; n < 4; n++) {
                int bc = wn * 32 + n * 8 + g, br = ks * 8 + t4;
                bf[n][0] = Bs[br][bc];
                bf[n][1] = Bs[br + 4][bc];
            }
#pragma unroll
            for (int m = 0; m < 4; m++)
#pragma unroll
                for (int n = 0; n < 4; n++)
                    mma8(acc[m][n], af[m][0], af[m][1], af[m][2], af[m][3],
                         bf[n][0], bf[n][1]);
        }
        __syncthreads();
    }

#pragma unroll
    for (int m = 0; m < 4; m++) {
#pragma unroll
        for (int n = 0; n < 4; n++) {
            int row = row0 + wm * 64 + m * 16 + g;
            int col = col0 + wn * 32 + n * 8 + 2 * t4;
            float2 v0 = {acc[m][n][0] * scale, acc[m][n][1] * scale};
            float2 v1 = {acc[m][n][2] * scale, acc[m][n][3] * scale};
            if (HSPLIT) {
                int b = row >> 11, l = row & (LL - 1);
                int h = col >> 6, d = col & 63;
                size_t idx = ((size_t)(b * NH + h) * LL + l) * 64 + d;
                *(float2*)&C[idx] = v0;
                *(float2*)&C[idx + (size_t)8 * 64] = v1;
            } else {
                size_t idx = (size_t)row * N + col;
                *(float2*)&C[idx] = v0;
                *(float2*)&C[idx + (size_t)8 * N] = v1;
            }
        }
    }
}

// ---------------------------------------------------------------------------
// Kernel 3: flash attention, CTA = (128 q rows, 1 head, 1 batch).
// 8 warps, each owns 16 q-rows. K-tiles of 64. TF32 mma for S and PV.
// BM smem buffer is reused as the P (tf32) buffer (same-thread ownership).
// ---------------------------------------------------------------------------
__global__ __launch_bounds__(256) void attn_kernel() {
    extern __shared__ unsigned sm[];
    unsigned* qs = sm;                       // TQ x AST (tf32)
    unsigned* ks = qs + TQ * AST;            // TK x AST (tf32)
    unsigned* vs = ks + TK * AST;            // TK x AST (tf32)
    float* bs = (float*)(vs + TK * AST);     // TQ x AST (fp32 BM, then tf32 P)
    unsigned* ps = (unsigned*)bs;

    const int b = blockIdx.z, h = blockIdx.y, qt = blockIdx.x;
    const int tid = threadIdx.x, lane = tid & 31, wid = tid >> 5;
    const int g = lane >> 2, t4 = lane & 3;
    const int wrow = wid * 16;

    const float* Qp = g_Qh + ((size_t)(b * NH + h) * LL + qt * TQ) * DKV;
    const float* Kp = g_Kh + (size_t)(b * NH + h) * LL * DKV;
    const float* Vp = g_Vh + (size_t)(b * NH + h) * LL * DKV;
    const float* BMp = g_BM + ((size_t)b * LL + qt * TQ) * LL;

    // Q tile load (once)
#pragma unroll
    for (int i = 0; i < 8; i++) {
        int f = tid + i * 256;
        int r = f >> 4, c4 = (f & 15) * 4;
        float4 v = *(const float4*)(Qp + (size_t)r * DKV + c4);
        uint4 u = {f2tf(v.x), f2tf(v.y), f2tf(v.z), f2tf(v.w)};
        *(uint4*)&qs[r * AST + c4] = u;
    }

    float m_i[2] = {-1e30f, -1e30f};
    float l_i[2] = {0.f, 0.f};
    float oacc[8][4];
#pragma unroll
    for (int nf = 0; nf < 8; nf++)
#pragma unroll
        for (int i = 0; i < 4; i++) oacc[nf][i] = 0.f;

    for (int kt = 0; kt < LL / TK; kt++) {
        __syncthreads();  // protect smem reuse from previous iteration
        // K + V tiles (64x64 each)
#pragma unroll
        for (int i = 0; i < 4; i++) {
            int f = tid + i * 256;
            int r = f >> 4, c4 = (f & 15) * 4;
            float4 v = *(const float4*)(Kp + (size_t)(kt * TK + r) * DKV + c4);
            uint4 u = {f2tf(v.x), f2tf(v.y), f2tf(v.z), f2tf(v.w)};
            *(uint4*)&ks[r * AST + c4] = u;
            float4 w = *(const float4*)(Vp + (size_t)(kt * TK + r) * DKV + c4);
            uint4 uw = {f2tf(w.x), f2tf(w.y), f2tf(w.z), f2tf(w.w)};
            *(uint4*)&vs[r * AST + c4] = uw;
        }
        // BM tile (128x64 fp32)
#pragma unroll
        for (int i = 0; i < 8; i++) {
            int f = tid + i * 256;
            int r = f >> 4, c4 = (f & 15) * 4;
            float4 v = *(const float4*)(BMp + (size_t)r * LL + kt * TK + c4);
            *(float4*)&bs[r * AST + c4] = v;
        }
        __syncthreads();

        // S = Qs @ K^T   (Q pre-scaled by 1/temperature at projection)
        float sacc[8][4];
#pragma unroll
        for (int nf = 0; nf < 8; nf++)
#pragma unroll
            for (int i = 0; i < 4; i++) sacc[nf][i] = 0.f;
#pragma unroll
        for (int kk = 0; kk < 8; kk++) {
            int ac = kk * 8 + t4;
            unsigned a0 = qs[(wrow + g) * AST + ac];
            unsigned a1 = qs[(wrow + g + 8) * AST + ac];
            unsigned a2 = qs[(wrow + g) * AST + ac + 4];
            unsigned a3 = qs[(wrow + g + 8) * AST + ac + 4];
#pragma unroll
            for (int nf = 0; nf < 8; nf++) {
                unsigned b0 = ks[(nf * 8 + g) * AST + ac];
                unsigned b1 = ks[(nf * 8 + g) * AST + ac + 4];
                mma8(sacc[nf], a0, a1, a2, a3, b0, b1);
            }
        }

        // bias/mask + online softmax
        float mloc[2] = {-1e30f, -1e30f};
#pragma unroll
        for (int nf = 0; nf < 8; nf++) {
            int col = nf * 8 + 2 * t4;
#pragma unroll
            for (int rr = 0; rr < 2; rr++) {
                int row = wrow + g + rr * 8;
                float b0 = bs[row * AST + col];
                float b1 = bs[row * AST + col + 1];
                float s0 = sacc[nf][rr * 2 + 0];
                float s1 = sacc[nf][rr * 2 + 1];
                s0 = (b0 <= -5000.f) ? NEGV : s0 + b0;
                s1 = (b1 <= -5000.f) ? NEGV : s1 + b1;
                sacc[nf][rr * 2 + 0] = s0;
                sacc[nf][rr * 2 + 1] = s1;
                mloc[rr] = fmaxf(mloc[rr], fmaxf(s0, s1));
            }
        }
#pragma unroll
        for (int rr = 0; rr < 2; rr++) {
            mloc[rr] = fmaxf(mloc[rr], __shfl_xor_sync(0xffffffffu, mloc[rr], 1));
            mloc[rr] = fmaxf(mloc[rr], __shfl_xor_sync(0xffffffffu, mloc[rr], 2));
        }
        float alpha[2], lsum[2] = {0.f, 0.f};
#pragma unroll
        for (int rr = 0; rr < 2; rr++) {
            float mn = fmaxf(m_i[rr], mloc[rr]);
            alpha[rr] = __expf(m_i[rr] - mn);
            m_i[rr] = mn;
        }
        // P = exp(S - m); write as tf32 into the BM buffer (same-thread reuse)
#pragma unroll
        for (int nf = 0; nf < 8; nf++) {
            int col = nf * 8 + 2 * t4;
#pragma unroll
            for (int rr = 0; rr < 2; rr++) {
                int row = wrow + g + rr * 8;
                float p0 = __expf(sacc[nf][rr * 2 + 0] - m_i[rr]);
                float p1 = __expf(sacc[nf][rr * 2 + 1] - m_i[rr]);
                lsum[rr] += p0 + p1;
                ps[row * AST + col] = f2tf(p0);
                ps[row * AST + col + 1] = f2tf(p1);
            }
        }
#pragma unroll
        for (int rr = 0; rr < 2; rr++) {
            lsum[rr] += __shfl_xor_sync(0xffffffffu, lsum[rr], 1);
            lsum[rr] += __shfl_xor_sync(0xffffffffu, lsum[rr], 2);
            l_i[rr] = l_i[rr] * alpha[rr] + lsum[rr];
        }
#pragma unroll
        for (int nf = 0; nf < 8; nf++) {
            oacc[nf][0] *= alpha[0];
            oacc[nf][1] *= alpha[0];
            oacc[nf][2] *= alpha[1];
            oacc[nf][3] *= alpha[1];
        }
        __syncwarp();  // P stores visible; each warp reads only its own rows

        // O += P @ V
#pragma unroll
        for (int kk = 0; kk < 8; kk++) {
            int ac = kk * 8 + t4;
            unsigned a0 = ps[(wrow + g) * AST + ac];
            unsigned a1 = ps[(wrow + g + 8) * AST + ac];
            unsigned a2 = ps[(wrow + g) * AST + ac + 4];
            unsigned a3 = ps[(wrow + g + 8) * AST + ac + 4];
#pragma unroll
            for (int nf = 0; nf < 8; nf++) {
                unsigned b0 = vs[(kk * 8 + t4) * AST + nf * 8 + g];
                unsigned b1 = vs[(kk * 8 + t4 + 4) * AST + nf * 8 + g];
                mma8(oacc[nf], a0, a1, a2, a3, b0, b1);
            }
        }
    }

    // write O[b][l][h*64+d]
    float inv0 = 1.f / l_i[0], inv1 = 1.f / l_i[1];
#pragma unroll
    for (int nf = 0; nf < 8; nf++) {
        int col = nf * 8 + 2 * t4;
        int row = qt * TQ + wrow + g;
        size_t idx = ((size_t)b * LL + row) * DM + h * DKV + col;
        float2 v0 = {oacc[nf][0] * inv0, oacc[nf][1] * inv0};
        float2 v1 = {oacc[nf][2] * inv1, oacc[nf][3] * inv1};
        *(float2*)&g_O[idx] = v0;
        *(float2*)&g_O[idx + (size_t)8 * DM] = v1;
    }
}

// ---------------------------------------------------------------------------
// Launch
// ---------------------------------------------------------------------------
#define ATTN_SMEM ((TQ * AST + TK * AST + TK * AST + TQ * AST) * 4)

extern "C" void kernel_launch(void* const* d_in, const int* in_sizes, int n_in,
                              void* d_out, int out_size) {
    const float* q = (const float*)d_in[0];
    const float* k = (const float*)d_in[1];
    const float* v = (const float*)d_in[2];
    const int* mask = (const int*)d_in[3];
    const float* bias = (const float*)d_in[4];
    const float* w_qs = (const float*)d_in[5];
    const float* w_ks = (const float*)d_in[6];
    const float* w_vs = (const float*)d_in[7];
    const float* w_fc = (const float*)d_in[8];
    float* out = (float*)d_out;

    float *Qh, *Kh, *Vh, *BM, *O;
    cudaGetSymbolAddress((void**)&Qh, g_Qh);
    cudaGetSymbolAddress((void**)&Kh, g_Kh);
    cudaGetSymbolAddress((void**)&Vh, g_Vh);
    cudaGetSymbolAddress((void**)&BM, g_BM);
    cudaGetSymbolAddress((void**)&O, g_O);

    cudaFuncSetAttribute(attn_kernel,
                         cudaFuncAttributeMaxDynamicSharedMemorySize,
                         ATTN_SMEM);

    // 1. fuse mask+bias (8M elems, x4 vectorized)
    fuse_bm_kernel<<<(BB * LL * LL) / (4 * 256), 256>>>(
        (const int4*)mask, (const float4*)bias, (float4*)BM);

    // 2. projections (head-split outputs; Q pre-scaled by 1/sqrt(64))
    dim3 grid(DM / 128, (BB * LL) / 128);
    gemm_tf32<true><<<grid, 256>>>(q, w_qs, Qh, BB * LL, DM, DM, 0.125f);
    gemm_tf32<true><<<grid, 256>>>(k, w_ks, Kh, BB * LL, DM, DM, 1.0f);
    gemm_tf32<true><<<grid, 256>>>(v, w_vs, Vh, BB * LL, DM, DM, 1.0f);

    // 3. attention
    attn_kernel<<<dim3(LL / TQ, NH, BB), 256, ATTN_SMEM>>>();

    // 4. output projection
    gemm_tf32<false><<<grid, 256>>>(O, w_fc, out, BB * LL, DM, DM, 1.0f);
}

// round 5
// speedup vs baseline: 2.7957x; 2.7957x over previous
#include <cuda_runtime.h>
#include <cuda_fp16.h>

#define BB 2
#define LL 2048
#define DM 1024
#define NH 16
#define DKV 64
#define NEGV (-10000.0f)
#define TQ 128
#define TK 64

// Scratch (device globals: allocation-free per harness rules)
__device__ __half g_Qh[(size_t)BB * NH * LL * DKV];
__device__ __half g_Kh[(size_t)BB * NH * LL * DKV];
__device__ __half g_Vh[(size_t)BB * NH * LL * DKV];
__device__ float g_BM[(size_t)BB * LL * LL];
__device__ float g_O[(size_t)BB * LL * DM];

__device__ __forceinline__ unsigned pack2(float x, float y) {
    __half2 h = __floats2half2_rn(x, y);
    return *reinterpret_cast<unsigned*>(&h);
}

__device__ __forceinline__ unsigned s2u(const void* p) {
    return (unsigned)__cvta_generic_to_shared(p);
}

__device__ __forceinline__ void ldsm4(unsigned& r0, unsigned& r1, unsigned& r2,
                                      unsigned& r3, unsigned addr) {
    asm volatile("ldmatrix.sync.aligned.m8n8.x4.shared.b16 {%0,%1,%2,%3},[%4];"
                 : "=r"(r0), "=r"(r1), "=r"(r2), "=r"(r3)
                 : "r"(addr));
}

__device__ __forceinline__ void ldsm4t(unsigned& r0, unsigned& r1, unsigned& r2,
                                       unsigned& r3, unsigned addr) {
    asm volatile(
        "ldmatrix.sync.aligned.m8n8.x4.trans.shared.b16 {%0,%1,%2,%3},[%4];"
        : "=r"(r0), "=r"(r1), "=r"(r2), "=r"(r3)
        : "r"(addr));
}

__device__ __forceinline__ void mma16(float* c, unsigned a0, unsigned a1,
                                      unsigned a2, unsigned a3, unsigned b0,
                                      unsigned b1) {
    asm volatile(
        "mma.sync.aligned.m16n8k16.row.col.f32.f16.f16.f32 "
        "{%0,%1,%2,%3},{%4,%5,%6,%7},{%8,%9},{%0,%1,%2,%3};"
        : "+f"(c[0]), "+f"(c[1]), "+f"(c[2]), "+f"(c[3])
        : "r"(a0), "r"(a1), "r"(a2), "r"(a3), "r"(b0), "r"(b1));
}

// ---------------------------------------------------------------------------
// Kernel 1: fuse mask+bias into one fp32 tensor.
// ---------------------------------------------------------------------------
__global__ void fuse_bm_kernel(const int4* __restrict__ mask,
                               const float4* __restrict__ bias,
                               float4* __restrict__ bm) {
    int i = blockIdx.x * blockDim.x + threadIdx.x;
    int4 m = mask[i];
    float4 bv = bias[i];
    float4 r;
    r.x = m.x ? bv.x : NEGV;
    r.y = m.y ? bv.y : NEGV;
    r.z = m.z ? bv.z : NEGV;
    r.w = m.w ? bv.w : NEGV;
    bm[i] = r;
}

// ---------------------------------------------------------------------------
// Kernel 2: fp16 tiled GEMM, C = A(fp32)@B(fp32) * scale, fp32 accumulate.
// 128x128x32 tiles, 8 warps (2x4), warp tile 64x32, m16n8k16 + ldmatrix.
// Double-buffered smem with register prefetch: one sync per K-tile.
// HSPLIT: C is __half, written to head-split layout [b][h][l][64].
// ---------------------------------------------------------------------------
template <bool HSPLIT>
__global__ __launch_bounds__(256) void gemm_f16(const float* __restrict__ A,
                                                const float* __restrict__ B,
                                                void* __restrict__ Cv, int M,
                                                int N, int K, float scale) {
    __shared__ __half As[2][128][40];   // pad 8: 80B stride, conflict-free
    __shared__ __half Bs[2][32][136];   // pad 8: 272B stride, conflict-free
    const int tid = threadIdx.x, lane = tid & 31, wid = tid >> 5;
    const int g = lane >> 2, t4 = lane & 3;
    const int wm = wid >> 2, wn = wid & 3;
    const int row0 = blockIdx.y * 128, col0 = blockIdx.x * 128;
    // ldmatrix lane mapping (A-style and trans-B-style share it)
    const int arow = (lane & 7) + ((lane >> 3) & 1) * 8;
    const int acol = (lane >> 4) * 8;

    float acc[4][4][4];
#pragma unroll
    for (int m = 0; m < 4; m++)
#pragma unroll
        for (int n = 0; n < 4; n++)
#pragma unroll
            for (int i = 0; i < 4; i++) acc[m][n][i] = 0.f;

    float4 av[4], bv[4];
    auto ldA = [&](int kt) {
#pragma unroll
        for (int i = 0; i < 4; i++) {
            int f = tid + i * 256, r = f >> 3, c4 = (f & 7) * 4;
            av[i] = *(const float4*)(A + (size_t)(row0 + r) * K + kt * 32 + c4);
        }
    };
    auto ldB = [&](int kt) {
#pragma unroll
        for (int i = 0; i < 4; i++) {
            int f = tid + i * 256, r = f >> 5, c4 = (f & 31) * 4;
            bv[i] = *(const float4*)(B + (size_t)(kt * 32 + r) * N + col0 + c4);
        }
    };
    auto stage = [&](int buf) {
#pragma unroll
        for (int i = 0; i < 4; i++) {
            int f = tid + i * 256, r = f >> 3, c4 = (f & 7) * 4;
            uint2 u = {pack2(av[i].x, av[i].y), pack2(av[i].z, av[i].w)};
            *(uint2*)&As[buf][r][c4] = u;
        }
#pragma unroll
        for (int i = 0; i < 4; i++) {
            int f = tid + i * 256, r = f >> 5, c4 = (f & 31) * 4;
            uint2 u = {pack2(bv[i].x, bv[i].y), pack2(bv[i].z, bv[i].w)};
            *(uint2*)&Bs[buf][r][c4] = u;
        }
    };

    ldA(0);
    ldB(0);
    stage(0);
    __syncthreads();
    const int nk = K / 32;

    for (int kt = 0; kt < nk; kt++) {
        int cur = kt & 1;
        if (kt + 1 < nk) {
            ldA(kt + 1);
            ldB(kt + 1);
        }
#pragma unroll
        for (int kk = 0; kk < 2; kk++) {
            unsigned af[4][4];
#pragma unroll
            for (int m = 0; m < 4; m++)
                ldsm4(af[m][0], af[m][1], af[m][2], af[m][3],
                      s2u(&As[cur][wm * 64 + m * 16 + arow][kk * 16 + acol]));
            unsigned bf[4][2];
#pragma unroll
            for (int np = 0; np < 2; np++) {
                unsigned r0, r1, r2, r3;
                ldsm4t(r0, r1, r2, r3,
                       s2u(&Bs[cur][kk * 16 + arow][wn * 32 + np * 16 + acol]));
                bf[np * 2][0] = r0;
                bf[np * 2][1] = r1;
                bf[np * 2 + 1][0] = r2;
                bf[np * 2 + 1][1] = r3;
            }
#pragma unroll
            for (int m = 0; m < 4; m++)
#pragma unroll
                for (int n = 0; n < 4; n++)
                    mma16(acc[m][n], af[m][0], af[m][1], af[m][2], af[m][3],
                          bf[n][0], bf[n][1]);
        }
        if (kt + 1 < nk) stage(cur ^ 1);
        __syncthreads();
    }

#pragma unroll
    for (int m = 0; m < 4; m++) {
#pragma unroll
        for (int n = 0; n < 4; n++) {
            int row = row0 + wm * 64 + m * 16 + g;
            int col = col0 + wn * 32 + n * 8 + 2 * t4;
            if (HSPLIT) {
                __half* C = (__half*)Cv;
                int b = row >> 11, l = row & (LL - 1);
                int h = col >> 6, d = col & 63;
                size_t idx = ((size_t)(b * NH + h) * LL + l) * 64 + d;
                *(__half2*)&C[idx] = __floats2half2_rn(acc[m][n][0] * scale,
                                                       acc[m][n][1] * scale);
                *(__half2*)&C[idx + (size_t)8 * 64] = __floats2half2_rn(
                    acc[m][n][2] * scale, acc[m][n][3] * scale);
            } else {
                float* C = (float*)Cv;
                size_t idx = (size_t)row * N + col;
                float2 v0 = {acc[m][n][0] * scale, acc[m][n][1] * scale};
                float2 v1 = {acc[m][n][2] * scale, acc[m][n][3] * scale};
                *(float2*)&C[idx] = v0;
                *(float2*)&C[idx + (size_t)8 * N] = v1;
            }
        }
    }
}

// ---------------------------------------------------------------------------
// Kernel 3: flash attention, CTA = (128 q rows, 1 head). fp16 mma + ldmatrix.
// ---------------------------------------------------------------------------
#define QS_OFF 0
#define KS_OFF (128 * 72 * 2)
#define VS_OFF (KS_OFF + 64 * 72 * 2)
#define BM_OFF (VS_OFF + 64 * 72 * 2)
#define PS_OFF (BM_OFF + 128 * 68 * 4)
#define ATTN_SMEM (PS_OFF + 128 * 72 * 2)  // 90112 B

__global__ __launch_bounds__(256, 2) void attn_kernel() {
    extern __shared__ char smraw[];
    __half* Qs = (__half*)(smraw + QS_OFF);   // [128][72]
    __half* Ks = (__half*)(smraw + KS_OFF);   // [64][72]
    __half* Vs = (__half*)(smraw + VS_OFF);   // [64][72]
    float* BMs = (float*)(smraw + BM_OFF);    // [128][68]
    __half* Ps = (__half*)(smraw + PS_OFF);   // [128][72]

    const int b = blockIdx.z, h = blockIdx.y, qt = blockIdx.x;
    const int tid = threadIdx.x, lane = tid & 31, wid = tid >> 5;
    const int g = lane >> 2, t4 = lane & 3;
    const int wrow = wid * 16;
    // ldmatrix lane mappings
    const int arow = (lane & 7) + ((lane >> 3) & 1) * 8;  // A-style / trans-B
    const int acol = (lane >> 4) * 8;
    const int brow = (lane & 7) + (lane >> 4) * 8;        // non-trans B (S)
    const int bcol = ((lane >> 3) & 1) * 8;

    const __half* Qp = g_Qh + ((size_t)(b * NH + h) * LL + qt * TQ) * DKV;
    const __half* Kp = g_Kh + (size_t)(b * NH + h) * LL * DKV;
    const __half* Vp = g_Vh + (size_t)(b * NH + h) * LL * DKV;
    const float* BMp = g_BM + ((size_t)b * LL + qt * TQ) * LL;

    // Q tile (once): 128x64 half, straight uint4 copy
#pragma unroll
    for (int i = 0; i < 4; i++) {
        int f = tid + i * 256, r = f >> 3, c8 = (f & 7) * 8;
        *(uint4*)&Qs[r * 72 + c8] = *(const uint4*)(Qp + (size_t)r * 64 + c8);
    }

    float m_i[2] = {-1e30f, -1e30f};
    float l_i[2] = {0.f, 0.f};
    float oacc[8][4];
#pragma unroll
    for (int nf = 0; nf < 8; nf++)
#pragma unroll
        for (int i = 0; i < 4; i++) oacc[nf][i] = 0.f;

    for (int kt = 0; kt < LL / TK; kt++) {
        __syncthreads();
        // K + V tiles: 64x64 half each
#pragma unroll
        for (int i = 0; i < 2; i++) {
            int f = tid + i * 256, r = f >> 3, c8 = (f & 7) * 8;
            *(uint4*)&Ks[r * 72 + c8] =
                *(const uint4*)(Kp + (size_t)(kt * TK + r) * 64 + c8);
            *(uint4*)&Vs[r * 72 + c8] =
                *(const uint4*)(Vp + (size_t)(kt * TK + r) * 64 + c8);
        }
        // BM tile: 128x64 fp32
#pragma unroll
        for (int i = 0; i < 8; i++) {
            int f = tid + i * 256, r = f >> 4, c4 = (f & 15) * 4;
            *(float4*)&BMs[r * 68 + c4] =
                *(const float4*)(BMp + (size_t)r * LL + kt * TK + c4);
        }
        __syncthreads();

        // S = Q @ K^T
        float sacc[8][4];
#pragma unroll
        for (int nf = 0; nf < 8; nf++)
#pragma unroll
            for (int i = 0; i < 4; i++) sacc[nf][i] = 0.f;
#pragma unroll
        for (int kk = 0; kk < 4; kk++) {
            unsigned a0, a1, a2, a3;
            ldsm4(a0, a1, a2, a3,
                  s2u(&Qs[(wrow + arow) * 72 + kk * 16 + acol]));
#pragma unroll
            for (int np = 0; np < 4; np++) {
                unsigned r0, r1, r2, r3;
                ldsm4(r0, r1, r2, r3,
                      s2u(&Ks[(np * 16 + brow) * 72 + kk * 16 + bcol]));
                mma16(sacc[np * 2], a0, a1, a2, a3, r0, r1);
                mma16(sacc[np * 2 + 1], a0, a1, a2, a3, r2, r3);
            }
        }

        // bias/mask + online softmax
        float mloc[2] = {-1e30f, -1e30f};
#pragma unroll
        for (int nf = 0; nf < 8; nf++) {
            int col = nf * 8 + 2 * t4;
#pragma unroll
            for (int rr = 0; rr < 2; rr++) {
                int row = wrow + g + rr * 8;
                float b0 = BMs[row * 68 + col];
                float b1 = BMs[row * 68 + col + 1];
                float s0 = sacc[nf][rr * 2 + 0];
                float s1 = sacc[nf][rr * 2 + 1];
                s0 = (b0 <= -5000.f) ? NEGV : s0 + b0;
                s1 = (b1 <= -5000.f) ? NEGV : s1 + b1;
                sacc[nf][rr * 2 + 0] = s0;
                sacc[nf][rr * 2 + 1] = s1;
                mloc[rr] = fmaxf(mloc[rr], fmaxf(s0, s1));
            }
        }
#pragma unroll
        for (int rr = 0; rr < 2; rr++) {
            mloc[rr] = fmaxf(mloc[rr], __shfl_xor_sync(0xffffffffu, mloc[rr], 1));
            mloc[rr] = fmaxf(mloc[rr], __shfl_xor_sync(0xffffffffu, mloc[rr], 2));
        }
        float alpha[2], lsum[2] = {0.f, 0.f};
#pragma unroll
        for (int rr = 0; rr < 2; rr++) {
            float mn = fmaxf(m_i[rr], mloc[rr]);
            alpha[rr] = __expf(m_i[rr] - mn);
            m_i[rr] = mn;
        }
        // P = exp(S - m) as half into Ps (own-warp rows only)
#pragma unroll
        for (int nf = 0; nf < 8; nf++) {
            int col = nf * 8 + 2 * t4;
#pragma unroll
            for (int rr = 0; rr < 2; rr++) {
                int row = wrow + g + rr * 8;
                float p0 = __expf(sacc[nf][rr * 2 + 0] - m_i[rr]);
                float p1 = __expf(sacc[nf][rr * 2 + 1] - m_i[rr]);
                lsum[rr] += p0 + p1;
                *(__half2*)&Ps[row * 72 + col] = __floats2half2_rn(p0, p1);
            }
        }
#pragma unroll
        for (int rr = 0; rr < 2; rr++) {
            lsum[rr] += __shfl_xor_sync(0xffffffffu, lsum[rr], 1);
            lsum[rr] += __shfl_xor_sync(0xffffffffu, lsum[rr], 2);
            l_i[rr] = l_i[rr] * alpha[rr] + lsum[rr];
        }
#pragma unroll
        for (int nf = 0; nf < 8; nf++) {
            oacc[nf][0] *= alpha[0];
            oacc[nf][1] *= alpha[0];
            oacc[nf][2] *= alpha[1];
            oacc[nf][3] *= alpha[1];
        }
        __syncwarp();  // P visible; each warp reads only its own rows

        // O += P @ V
#pragma unroll
        for (int kk = 0; kk < 4; kk++) {
            unsigned a0, a1, a2, a3;
            ldsm4(a0, a1, a2, a3,
                  s2u(&Ps[(wrow + arow) * 72 + kk * 16 + acol]));
#pragma unroll
            for (int np = 0; np < 4; np++) {
                unsigned r0, r1, r2, r3;
                ldsm4t(r0, r1, r2, r3,
                       s2u(&Vs[(kk * 16 + arow) * 72 + np * 16 + acol]));
                mma16(oacc[np * 2], a0, a1, a2, a3, r0, r1);
                mma16(oacc[np * 2 + 1], a0, a1, a2, a3, r2, r3);
            }
        }
    }

    // write O[b][l][h*64+d] fp32
    float inv0 = 1.f / l_i[0], inv1 = 1.f / l_i[1];
#pragma unroll
    for (int nf = 0; nf < 8; nf++) {
        int col = nf * 8 + 2 * t4;
        int row = qt * TQ + wrow + g;
        size_t idx = ((size_t)b * LL + row) * DM + h * DKV + col;
        float2 v0 = {oacc[nf][0] * inv0, oacc[nf][1] * inv0};
        float2 v1 = {oacc[nf][2] * inv1, oacc[nf][3] * inv1};
        *(float2*)&g_O[idx] = v0;
        *(float2*)&g_O[idx + (size_t)8 * DM] = v1;
    }
}

// ---------------------------------------------------------------------------
// Launch
// ---------------------------------------------------------------------------
extern "C" void kernel_launch(void* const* d_in, const int* in_sizes, int n_in,
                              void* d_out, int out_size) {
    const float* q = (const float*)d_in[0];
    const float* k = (const float*)d_in[1];
    const float* v = (const float*)d_in[2];
    const int* mask = (const int*)d_in[3];
    const float* bias = (const float*)d_in[4];
    const float* w_qs = (const float*)d_in[5];
    const float* w_ks = (const float*)d_in[6];
    const float* w_vs = (const float*)d_in[7];
    const float* w_fc = (const float*)d_in[8];
    float* out = (float*)d_out;

    __half *Qh, *Kh, *Vh;
    float *BM, *O;
    cudaGetSymbolAddress((void**)&Qh, g_Qh);
    cudaGetSymbolAddress((void**)&Kh, g_Kh);
    cudaGetSymbolAddress((void**)&Vh, g_Vh);
    cudaGetSymbolAddress((void**)&BM, g_BM);
    cudaGetSymbolAddress((void**)&O, g_O);

    cudaFuncSetAttribute(attn_kernel,
                         cudaFuncAttributeMaxDynamicSharedMemorySize,
                         ATTN_SMEM);

    // 1. fuse mask+bias
    fuse_bm_kernel<<<(BB * LL * LL) / (4 * 256), 256>>>(
        (const int4*)mask, (const float4*)bias, (float4*)BM);

    // 2. projections (half head-split outputs; Q pre-scaled by 1/8)
    dim3 grid(DM / 128, (BB * LL) / 128);
    gemm_f16<true><<<grid, 256>>>(q, w_qs, Qh, BB * LL, DM, DM, 0.125f);
    gemm_f16<true><<<grid, 256>>>(k, w_ks, Kh, BB * LL, DM, DM, 1.0f);
    gemm_f16<true><<<grid, 256>>>(v, w_vs, Vh, BB * LL, DM, DM, 1.0f);

    // 3. attention
    attn_kernel<<<dim3(LL / TQ, NH, BB), 256, ATTN_SMEM>>>();

    // 4. output projection (fp32 in/out)
    gemm_f16<false><<<grid, 256>>>(O, w_fc, out, BB * LL, DM, DM, 1.0f);
}

// round 9
// speedup vs baseline: 3.1763x; 1.1361x over previous
#include <cuda_runtime.h>
#include <cuda_fp16.h>

#define BB 2
#define LL 2048
#define DM 1024
#define NH 16
#define DKV 64
#define NEGV (-10000.0f)
#define TQ 128
#define TK 64
#define NT (LL / TK)

// Scratch (device globals: allocation-free per harness rules)
__device__ __align__(16) __half g_hq[(size_t)BB * LL * DM];
__device__ __align__(16) __half g_hk[(size_t)BB * LL * DM];
__device__ __align__(16) __half g_hv[(size_t)BB * LL * DM];
__device__ __align__(16) __half g_hw[4][(size_t)DM * DM];
__device__ __align__(16) __half g_Qh[(size_t)BB * NH * LL * DKV];
__device__ __align__(16) __half g_Kh[(size_t)BB * NH * LL * DKV];
__device__ __align__(16) __half g_Vh[(size_t)BB * NH * LL * DKV];
__device__ float g_BM[(size_t)BB * LL * LL];
__device__ __align__(16) __half g_O[(size_t)BB * LL * DM];

__device__ __forceinline__ unsigned pack2(float x, float y) {
    __half2 h = __floats2half2_rn(x, y);
    return *reinterpret_cast<unsigned*>(&h);
}

__device__ __forceinline__ unsigned s2u(const void* p) {
    return (unsigned)__cvta_generic_to_shared(p);
}

__device__ __forceinline__ void cpa16(void* dst, const void* src) {
    asm volatile("cp.async.cg.shared.global [%0],[%1],16;" ::"r"(s2u(dst)),
                 "l"(src));
}
#define CPCOMMIT asm volatile("cp.async.commit_group;")
#define CPWAIT(n) asm volatile("cp.async.wait_group %0;" ::"n"(n))

__device__ __forceinline__ void ldsm4(unsigned& r0, unsigned& r1, unsigned& r2,
                                      unsigned& r3, unsigned addr) {
    asm volatile("ldmatrix.sync.aligned.m8n8.x4.shared.b16 {%0,%1,%2,%3},[%4];"
                 : "=r"(r0), "=r"(r1), "=r"(r2), "=r"(r3)
                 : "r"(addr));
}

__device__ __forceinline__ void ldsm4t(unsigned& r0, unsigned& r1, unsigned& r2,
                                       unsigned& r3, unsigned addr) {
    asm volatile(
        "ldmatrix.sync.aligned.m8n8.x4.trans.shared.b16 {%0,%1,%2,%3},[%4];"
        : "=r"(r0), "=r"(r1), "=r"(r2), "=r"(r3)
        : "r"(addr));
}

__device__ __forceinline__ void mma16(float* c, unsigned a0, unsigned a1,
                                      unsigned a2, unsigned a3, unsigned b0,
                                      unsigned b1) {
    asm volatile(
        "mma.sync.aligned.m16n8k16.row.col.f32.f16.f16.f32 "
        "{%0,%1,%2,%3},{%4,%5,%6,%7},{%8,%9},{%0,%1,%2,%3};"
        : "+f"(c[0]), "+f"(c[1]), "+f"(c[2]), "+f"(c[3])
        : "r"(a0), "r"(a1), "r"(a2), "r"(a3), "r"(b0), "r"(b1));
}

// ---------------------------------------------------------------------------
// Kernel 0: bulk fp32 -> fp16 conversion of activations + weights.
// Blocks 0-1023:q 1024-2047:k 2048-3071:v then 4x256 blocks of weights.
// ---------------------------------------------------------------------------
struct CvtArgs {
    const float4* s[7];
    uint2* d[7];
};
__global__ __launch_bounds__(256) void cvt_kernel(CvtArgs a) {
    int bid = blockIdx.x;
    int ti, base;
    if (bid < 3072) {
        ti = bid >> 10;
        base = bid & 1023;
    } else {
        ti = 3 + ((bid - 3072) >> 8);
        base = (bid - 3072) & 255;
    }
    const float4* s = a.s[ti];
    uint2* d = a.d[ti];
    size_t off = (size_t)base * 1024 + threadIdx.x;
#pragma unroll
    for (int i = 0; i < 4; i++) {
        float4 v = s[off + i * 256];
        uint2 u;
        u.x = pack2(v.x, v.y);
        u.y = pack2(v.z, v.w);
        d[off + i * 256] = u;
    }
}

// ---------------------------------------------------------------------------
// Kernel 1: fuse mask+bias into one fp32 tensor.
// ---------------------------------------------------------------------------
__global__ void fuse_bm_kernel(const int4* __restrict__ mask,
                               const float4* __restrict__ bias,
                               float4* __restrict__ bm) {
    int i = blockIdx.x * blockDim.x + threadIdx.x;
    int4 m = mask[i];
    float4 bv = bias[i];
    float4 r;
    r.x = m.x ? bv.x : NEGV;
    r.y = m.y ? bv.y : NEGV;
    r.z = m.z ? bv.z : NEGV;
    r.w = m.w ? bv.w : NEGV;
    bm[i] = r;
}

// ---------------------------------------------------------------------------
// Kernel 2: pure-fp16 GEMM, C = A@B * scale, fp32 accumulate.
// 128x128x32 tiles, 8 warps (2x4), m16n8k16 + ldmatrix.
// 3-stage cp.async pipeline, no register staging, no cvt in hot loop.
// HSPLIT: C is __half head-split layout [b][h][l][64]; else fp32 row-major.
// ---------------------------------------------------------------------------
#define GA_ST 40
#define GB_ST 136
#define GA_SZ (128 * GA_ST)
#define GB_SZ (32 * GB_ST)
#define GEMM_SMEM ((3 * GA_SZ + 3 * GB_SZ) * 2)

template <bool HSPLIT>
__global__ __launch_bounds__(256) void gemm_f16(const __half* __restrict__ A,
                                                const __half* __restrict__ B,
                                                void* __restrict__ Cv, int M,
                                                int N, int K, float scale) {
    extern __shared__ __half gsm[];
    const int tid = threadIdx.x, lane = tid & 31, wid = tid >> 5;
    const int g = lane >> 2, t4 = lane & 3;
    const int wm = wid >> 2, wn = wid & 3;
    const int row0 = blockIdx.y * 128, col0 = blockIdx.x * 128;
    const int arow = (lane & 7) + ((lane >> 3) & 1) * 8;
    const int acol = (lane >> 4) * 8;

    float acc[4][4][4];
#pragma unroll
    for (int m = 0; m < 4; m++)
#pragma unroll
        for (int n = 0; n < 4; n++)
#pragma unroll
            for (int i = 0; i < 4; i++) acc[m][n][i] = 0.f;

    auto issue = [&](int kt) {
        int buf = kt % 3;
        __half* As = gsm + buf * GA_SZ;
        __half* Bs = gsm + 3 * GA_SZ + buf * GB_SZ;
#pragma unroll
        for (int i = 0; i < 2; i++) {
            int f = tid + i * 256, r = f >> 2, c8 = (f & 3) * 8;
            cpa16(As + r * GA_ST + c8,
                  A + (size_t)(row0 + r) * K + kt * 32 + c8);
        }
#pragma unroll
        for (int i = 0; i < 2; i++) {
            int f = tid + i * 256, r = f >> 4, c8 = (f & 15) * 8;
            cpa16(Bs + r * GB_ST + c8,
                  B + (size_t)(kt * 32 + r) * N + col0 + c8);
        }
    };

    const int nk = K / 32;
    issue(0);
    CPCOMMIT;
    issue(1);
    CPCOMMIT;

    for (int kt = 0; kt < nk; kt++) {
        CPWAIT(1);
        __syncthreads();
        int buf = kt % 3;
        __half* As = gsm + buf * GA_SZ;
        __half* Bs = gsm + 3 * GA_SZ + buf * GB_SZ;
#pragma unroll
        for (int kk = 0; kk < 2; kk++) {
            unsigned af[4][4];
#pragma unroll
            for (int m = 0; m < 4; m++)
                ldsm4(af[m][0], af[m][1], af[m][2], af[m][3],
                      s2u(As + (wm * 64 + m * 16 + arow) * GA_ST + kk * 16 +
                          acol));
            unsigned bf[4][2];
#pragma unroll
            for (int np = 0; np < 2; np++) {
                unsigned r0, r1, r2, r3;
                ldsm4t(r0, r1, r2, r3,
                       s2u(Bs + (kk * 16 + arow) * GB_ST + wn * 32 + np * 16 +
                           acol));
                bf[np * 2][0] = r0;
                bf[np * 2][1] = r1;
                bf[np * 2 + 1][0] = r2;
                bf[np * 2 + 1][1] = r3;
            }
#pragma unroll
            for (int m = 0; m < 4; m++)
#pragma unroll
                for (int n = 0; n < 4; n++)
                    mma16(acc[m][n], af[m][0], af[m][1], af[m][2], af[m][3],
                          bf[n][0], bf[n][1]);
        }
        if (kt + 2 < nk) issue(kt + 2);
        CPCOMMIT;
    }

#pragma unroll
    for (int m = 0; m < 4; m++) {
#pragma unroll
        for (int n = 0; n < 4; n++) {
            int row = row0 + wm * 64 + m * 16 + g;
            int col = col0 + wn * 32 + n * 8 + 2 * t4;
            if (HSPLIT) {
                __half* C = (__half*)Cv;
                int b = row >> 11, l = row & (LL - 1);
                int h = col >> 6, d = col & 63;
                size_t idx = ((size_t)(b * NH + h) * LL + l) * 64 + d;
                *(__half2*)&C[idx] = __floats2half2_rn(acc[m][n][0] * scale,
                                                       acc[m][n][1] * scale);
                *(__half2*)&C[idx + (size_t)8 * 64] = __floats2half2_rn(
                    acc[m][n][2] * scale, acc[m][n][3] * scale);
            } else {
                float* C = (float*)Cv;
                size_t idx = (size_t)row * N + col;
                float2 v0 = {acc[m][n][0] * scale, acc[m][n][1] * scale};
                float2 v1 = {acc[m][n][2] * scale, acc[m][n][3] * scale};
                *(float2*)&C[idx] = v0;
                *(float2*)&C[idx + (size_t)8 * N] = v1;
            }
        }
    }
}

// ---------------------------------------------------------------------------
// Kernel 3: flash attention. CTA = (128 q rows, 1 head).
// P kept in registers (S accumulator layout == PV A-fragment layout),
// BM loaded gmem->regs directly, K/V double-buffered via cp.async.
// ---------------------------------------------------------------------------
#define KV_SZ (64 * 72)
#define ATTN_SMEM ((128 * 72 + 4 * KV_SZ) * 2)  // 55296 B

__global__ __launch_bounds__(256, 2) void attn_kernel() {
    extern __shared__ __half smh[];
    __half* Qs = smh;                  // [128][72]
    __half* Ksb = smh + 128 * 72;      // [2][64][72]
    __half* Vsb = Ksb + 2 * KV_SZ;     // [2][64][72]

    const int b = blockIdx.z, h = blockIdx.y, qt = blockIdx.x;
    const int tid = threadIdx.x, lane = tid & 31, wid = tid >> 5;
    const int g = lane >> 2, t4 = lane & 3;
    const int wrow = wid * 16;
    const int arow = (lane & 7) + ((lane >> 3) & 1) * 8;  // A-style / trans-B
    const int acol = (lane >> 4) * 8;
    const int brow = (lane & 7) + (lane >> 4) * 8;        // non-trans B (S)
    const int bcol = ((lane >> 3) & 1) * 8;

    const __half* Qp = g_Qh + ((size_t)(b * NH + h) * LL + qt * TQ) * DKV;
    const __half* Kp = g_Kh + (size_t)(b * NH + h) * LL * DKV;
    const __half* Vp = g_Vh + (size_t)(b * NH + h) * LL * DKV;
    const float* BMp = g_BM + ((size_t)b * LL + qt * TQ) * LL;

    auto issue_kv = [&](int kt, int buf) {
#pragma unroll
        for (int i = 0; i < 2; i++) {
            int f = tid + i * 256, r = f >> 3, c8 = (f & 7) * 8;
            cpa16(Ksb + buf * KV_SZ + r * 72 + c8,
                  Kp + (size_t)(kt * TK + r) * 64 + c8);
            cpa16(Vsb + buf * KV_SZ + r * 72 + c8,
                  Vp + (size_t)(kt * TK + r) * 64 + c8);
        }
    };

    // Q tile (once) + first K/V tile, one cp.async group
#pragma unroll
    for (int i = 0; i < 4; i++) {
        int f = tid + i * 256, r = f >> 3, c8 = (f & 7) * 8;
        cpa16(Qs + r * 72 + c8, Qp + (size_t)r * 64 + c8);
    }
    issue_kv(0, 0);
    CPCOMMIT;

    float m_i[2] = {-1e30f, -1e30f};
    float l_i[2] = {0.f, 0.f};
    float oacc[8][4];
#pragma unroll
    for (int nf = 0; nf < 8; nf++)
#pragma unroll
        for (int i = 0; i < 4; i++) oacc[nf][i] = 0.f;

    for (int kt = 0; kt < NT; kt++) {
        int cur = kt & 1;
        CPWAIT(0);
        __syncthreads();
        if (kt + 1 < NT) {
            issue_kv(kt + 1, cur ^ 1);
            CPCOMMIT;
        }
        __half* Ks = Ksb + cur * KV_SZ;
        __half* Vs = Vsb + cur * KV_SZ;

        // BM batch 0 (nf 0..3): gmem -> regs, hidden under the S-mma
        float2 bm0[8], bm1[8];
#pragma unroll
        for (int nf = 0; nf < 4; nf++)
#pragma unroll
            for (int rr = 0; rr < 2; rr++)
                bm0[nf * 2 + rr] = *(const float2*)(
                    BMp + (size_t)(wrow + g + rr * 8) * LL + kt * TK + nf * 8 +
                    2 * t4);

        // S = Q @ K^T
        float sacc[8][4];
#pragma unroll
        for (int nf = 0; nf < 8; nf++)
#pragma unroll
            for (int i = 0; i < 4; i++) sacc[nf][i] = 0.f;
#pragma unroll
        for (int kk = 0; kk < 4; kk++) {
            unsigned a0, a1, a2, a3;
            ldsm4(a0, a1, a2, a3,
                  s2u(Qs + (wrow + arow) * 72 + kk * 16 + acol));
#pragma unroll
            for (int np = 0; np < 4; np++) {
                unsigned r0, r1, r2, r3;
                ldsm4(r0, r1, r2, r3,
                      s2u(Ks + (np * 16 + brow) * 72 + kk * 16 + bcol));
                mma16(sacc[np * 2], a0, a1, a2, a3, r0, r1);
                mma16(sacc[np * 2 + 1], a0, a1, a2, a3, r2, r3);
            }
        }

        // BM batch 1 (nf 4..7)
#pragma unroll
        for (int nf = 0; nf < 4; nf++)
#pragma unroll
            for (int rr = 0; rr < 2; rr++)
                bm1[nf * 2 + rr] = *(const float2*)(
                    BMp + (size_t)(wrow + g + rr * 8) * LL + kt * TK +
                    (nf + 4) * 8 + 2 * t4);

        // bias/mask + online softmax
        float mloc[2] = {-1e30f, -1e30f};
#pragma unroll
        for (int nf = 0; nf < 8; nf++) {
#pragma unroll
            for (int rr = 0; rr < 2; rr++) {
                float2 bm = (nf < 4) ? bm0[nf * 2 + rr] : bm1[(nf - 4) * 2 + rr];
                float s0 = sacc[nf][rr * 2 + 0];
                float s1 = sacc[nf][rr * 2 + 1];
                s0 = (bm.x <= -5000.f) ? NEGV : s0 + bm.x;
                s1 = (bm.y <= -5000.f) ? NEGV : s1 + bm.y;
                sacc[nf][rr * 2 + 0] = s0;
                sacc[nf][rr * 2 + 1] = s1;
                mloc[rr] = fmaxf(mloc[rr], fmaxf(s0, s1));
            }
        }
#pragma unroll
        for (int rr = 0; rr < 2; rr++) {
            mloc[rr] = fmaxf(mloc[rr], __shfl_xor_sync(0xffffffffu, mloc[rr], 1));
            mloc[rr] = fmaxf(mloc[rr], __shfl_xor_sync(0xffffffffu, mloc[rr], 2));
        }
        float alpha[2], lsum[2] = {0.f, 0.f};
#pragma unroll
        for (int rr = 0; rr < 2; rr++) {
            float mn = fmaxf(m_i[rr], mloc[rr]);
            alpha[rr] = __expf(m_i[rr] - mn);
            m_i[rr] = mn;
        }
        // P = exp(S - m), kept in sacc (registers)
#pragma unroll
        for (int nf = 0; nf < 8; nf++) {
#pragma unroll
            for (int rr = 0; rr < 2; rr++) {
                float p0 = __expf(sacc[nf][rr * 2 + 0] - m_i[rr]);
                float p1 = __expf(sacc[nf][rr * 2 + 1] - m_i[rr]);
                lsum[rr] += p0 + p1;
                sacc[nf][rr * 2 + 0] = p0;
                sacc[nf][rr * 2 + 1] = p1;
            }
        }
#pragma unroll
        for (int rr = 0; rr < 2; rr++) {
            lsum[rr] += __shfl_xor_sync(0xffffffffu, lsum[rr], 1);
            lsum[rr] += __shfl_xor_sync(0xffffffffu, lsum[rr], 2);
            l_i[rr] = l_i[rr] * alpha[rr] + lsum[rr];
        }
#pragma unroll
        for (int nf = 0; nf < 8; nf++) {
            oacc[nf][0] *= alpha[0];
            oacc[nf][1] *= alpha[0];
            oacc[nf][2] *= alpha[1];
            oacc[nf][3] *= alpha[1];
        }

        // O += P @ V : A-fragments packed directly from sacc (no smem!)
#pragma unroll
        for (int kk = 0; kk < 4; kk++) {
            unsigned a0 = pack2(sacc[2 * kk][0], sacc[2 * kk][1]);
            unsigned a1 = pack2(sacc[2 * kk][2], sacc[2 * kk][3]);
            unsigned a2 = pack2(sacc[2 * kk + 1][0], sacc[2 * kk + 1][1]);
            unsigned a3 = pack2(sacc[2 * kk + 1][2], sacc[2 * kk + 1][3]);
#pragma unroll
            for (int np = 0; np < 4; np++) {
                unsigned r0, r1, r2, r3;
                ldsm4t(r0, r1, r2, r3,
                       s2u(Vs + (kk * 16 + arow) * 72 + np * 16 + acol));
                mma16(oacc[np * 2], a0, a1, a2, a3, r0, r1);
                mma16(oacc[np * 2 + 1], a0, a1, a2, a3, r2, r3);
            }
        }
    }

    // write O[b][l][h*64+d] as half (consumed as half by the final GEMM)
    float inv0 = 1.f / l_i[0], inv1 = 1.f / l_i[1];
#pragma unroll
    for (int nf = 0; nf < 8; nf++) {
        int col = nf * 8 + 2 * t4;
        int row = qt * TQ + wrow + g;
        size_t idx = ((size_t)b * LL + row) * DM + h * DKV + col;
        *(__half2*)&g_O[idx] =
            __floats2half2_rn(oacc[nf][0] * inv0, oacc[nf][1] * inv0);
        *(__half2*)&g_O[idx + (size_t)8 * DM] =
            __floats2half2_rn(oacc[nf][2] * inv1, oacc[nf][3] * inv1);
    }
}

// ---------------------------------------------------------------------------
// Launch
// ---------------------------------------------------------------------------
extern "C" void kernel_launch(void* const* d_in, const int* in_sizes, int n_in,
                              void* d_out, int out_size) {
    const float* q = (const float*)d_in[0];
    const float* k = (const float*)d_in[1];
    const float* v = (const float*)d_in[2];
    const int* mask = (const int*)d_in[3];
    const float* bias = (const float*)d_in[4];
    float* out = (float*)d_out;

    __half *hq, *hk, *hv, *hw, *Qh, *Kh, *Vh, *O;
    float* BM;
    cudaGetSymbolAddress((void**)&hq, g_hq);
    cudaGetSymbolAddress((void**)&hk, g_hk);
    cudaGetSymbolAddress((void**)&hv, g_hv);
    cudaGetSymbolAddress((void**)&hw, g_hw);
    cudaGetSymbolAddress((void**)&Qh, g_Qh);
    cudaGetSymbolAddress((void**)&Kh, g_Kh);
    cudaGetSymbolAddress((void**)&Vh, g_Vh);
    cudaGetSymbolAddress((void**)&BM, g_BM);
    cudaGetSymbolAddress((void**)&O, g_O);
    size_t WSZ = (size_t)DM * DM;

    cudaFuncSetAttribute(attn_kernel,
                         cudaFuncAttributeMaxDynamicSharedMemorySize,
                         ATTN_SMEM);
    cudaFuncSetAttribute(gemm_f16<true>,
                         cudaFuncAttributeMaxDynamicSharedMemorySize,
                         GEMM_SMEM);
    cudaFuncSetAttribute(gemm_f16<false>,
                         cudaFuncAttributeMaxDynamicSharedMemorySize,
                         GEMM_SMEM);

    // 0. fp32->fp16 bulk convert (activations + 4 weight matrices)
    CvtArgs ca;
    ca.s[0] = (const float4*)q;
    ca.s[1] = (const float4*)k;
    ca.s[2] = (const float4*)v;
    ca.s[3] = (const float4*)d_in[5];
    ca.s[4] = (const float4*)d_in[6];
    ca.s[5] = (const float4*)d_in[7];
    ca.s[6] = (const float4*)d_in[8];
    ca.d[0] = (uint2*)hq;
    ca.d[1] = (uint2*)hk;
    ca.d[2] = (uint2*)hv;
    ca.d[3] = (uint2*)(hw + 0 * WSZ);
    ca.d[4] = (uint2*)(hw + 1 * WSZ);
    ca.d[5] = (uint2*)(hw + 2 * WSZ);
    ca.d[6] = (uint2*)(hw + 3 * WSZ);
    cvt_kernel<<<4096, 256>>>(ca);

    // 1. fuse mask+bias (fp32)
    fuse_bm_kernel<<<(BB * LL * LL) / (4 * 256), 256>>>(
        (const int4*)mask, (const float4*)bias, (float4*)BM);

    // 2. projections (half in/out, head-split; Q pre-scaled by 1/8)
    dim3 grid(DM / 128, (BB * LL) / 128);
    gemm_f16<true><<<grid, 256, GEMM_SMEM>>>(hq, hw + 0 * WSZ, Qh, BB * LL, DM,
                                             DM, 0.125f);
    gemm_f16<true><<<grid, 256, GEMM_SMEM>>>(hk, hw + 1 * WSZ, Kh, BB * LL, DM,
                                             DM, 1.0f);
    gemm_f16<true><<<grid, 256, GEMM_SMEM>>>(hv, hw + 2 * WSZ, Vh, BB * LL, DM,
                                             DM, 1.0f);

    // 3. attention
    attn_kernel<<<dim3(LL / TQ, NH, BB), 256, ATTN_SMEM>>>();

    // 4. output projection (half in, fp32 out)
    gemm_f16<false><<<grid, 256, GEMM_SMEM>>>(O, hw + 3 * WSZ, out, BB * LL,
                                              DM, DM, 1.0f);
}

// round 11
// speedup vs baseline: 3.4655x; 1.0910x over previous
#include <cuda_runtime.h>
#include <cuda_fp16.h>

#define BB 2
#define LL 2048
#define DM 1024
#define NH 16
#define DKV 64
#define NEGV (-10000.0f)
#define TQ 128
#define TK 64
#define NT (LL / TK)
#define L2E 1.4426950408889634f

// Scratch (device globals: allocation-free per harness rules)
__device__ __align__(16) __half g_hq[(size_t)BB * LL * DM];
__device__ __align__(16) __half g_hk[(size_t)BB * LL * DM];
__device__ __align__(16) __half g_hv[(size_t)BB * LL * DM];
__device__ __align__(16) __half g_hw[4][(size_t)DM * DM];
__device__ __align__(16) __half g_Qh[(size_t)BB * NH * LL * DKV];
__device__ __align__(16) __half g_Kh[(size_t)BB * NH * LL * DKV];
__device__ __align__(16) __half g_Vh[(size_t)BB * NH * LL * DKV];
__device__ float g_BM[(size_t)BB * LL * LL];
__device__ __align__(16) __half g_O[(size_t)BB * LL * DM];

__device__ __forceinline__ unsigned pack2(float x, float y) {
    __half2 h = __floats2half2_rn(x, y);
    return *reinterpret_cast<unsigned*>(&h);
}

__device__ __forceinline__ float ex2f(float x) {
    float y;
    asm("ex2.approx.f32 %0,%1;" : "=f"(y) : "f"(x));
    return y;
}

__device__ __forceinline__ unsigned s2u(const void* p) {
    return (unsigned)__cvta_generic_to_shared(p);
}

__device__ __forceinline__ void cpa16(void* dst, const void* src) {
    asm volatile("cp.async.cg.shared.global [%0],[%1],16;" ::"r"(s2u(dst)),
                 "l"(src));
}
#define CPCOMMIT asm volatile("cp.async.commit_group;")
#define CPWAIT(n) asm volatile("cp.async.wait_group %0;" ::"n"(n))

__device__ __forceinline__ void ldsm4(unsigned& r0, unsigned& r1, unsigned& r2,
                                      unsigned& r3, unsigned addr) {
    asm volatile("ldmatrix.sync.aligned.m8n8.x4.shared.b16 {%0,%1,%2,%3},[%4];"
                 : "=r"(r0), "=r"(r1), "=r"(r2), "=r"(r3)
                 : "r"(addr));
}

__device__ __forceinline__ void ldsm4t(unsigned& r0, unsigned& r1, unsigned& r2,
                                       unsigned& r3, unsigned addr) {
    asm volatile(
        "ldmatrix.sync.aligned.m8n8.x4.trans.shared.b16 {%0,%1,%2,%3},[%4];"
        : "=r"(r0), "=r"(r1), "=r"(r2), "=r"(r3)
        : "r"(addr));
}

__device__ __forceinline__ void mma16(float* c, unsigned a0, unsigned a1,
                                      unsigned a2, unsigned a3, unsigned b0,
                                      unsigned b1) {
    asm volatile(
        "mma.sync.aligned.m16n8k16.row.col.f32.f16.f16.f32 "
        "{%0,%1,%2,%3},{%4,%5,%6,%7},{%8,%9},{%0,%1,%2,%3};"
        : "+f"(c[0]), "+f"(c[1]), "+f"(c[2]), "+f"(c[3])
        : "r"(a0), "r"(a1), "r"(a2), "r"(a3), "r"(b0), "r"(b1));
}

// ---------------------------------------------------------------------------
// Kernel 0: merged prep. Blocks [0,4096): fp32->fp16 convert of activations
// + weights. Blocks [4096,12288): fuse mask+bias -> BM (fp32).
// ---------------------------------------------------------------------------
struct PrepArgs {
    const float4* s[7];
    uint2* d[7];
    const int4* mask;
    const float4* bias;
    float4* bm;
};
__global__ __launch_bounds__(256) void prep_kernel(PrepArgs a) {
    int bid = blockIdx.x;
    if (bid < 4096) {
        int ti, base;
        if (bid < 3072) {
            ti = bid >> 10;
            base = bid & 1023;
        } else {
            ti = 3 + ((bid - 3072) >> 8);
            base = (bid - 3072) & 255;
        }
        const float4* s = a.s[ti];
        uint2* d = a.d[ti];
        size_t off = (size_t)base * 1024 + threadIdx.x;
#pragma unroll
        for (int i = 0; i < 4; i++) {
            float4 v = s[off + i * 256];
            uint2 u;
            u.x = pack2(v.x, v.y);
            u.y = pack2(v.z, v.w);
            d[off + i * 256] = u;
        }
    } else {
        int i = (bid - 4096) * 256 + threadIdx.x;
        int4 m = a.mask[i];
        float4 bv = a.bias[i];
        float4 r;
        r.x = m.x ? bv.x : NEGV;
        r.y = m.y ? bv.y : NEGV;
        r.z = m.z ? bv.z : NEGV;
        r.w = m.w ? bv.w : NEGV;
        a.bm[i] = r;
    }
}

// ---------------------------------------------------------------------------
// GEMM body: pure-fp16, C = A@B * scale, fp32 accumulate. M=4096 N=K=1024.
// 128x128x32 tiles, 8 warps (2x4), m16n8k16 + ldmatrix, 3-stage cp.async.
// HSPLIT: C is __half head-split layout [b][h][l][64]; else fp32 row-major.
// ---------------------------------------------------------------------------
#define GA_ST 40
#define GB_ST 136
#define GA_SZ (128 * GA_ST)
#define GB_SZ (32 * GB_ST)
#define GEMM_SMEM ((3 * GA_SZ + 3 * GB_SZ) * 2)

template <bool HSPLIT>
__device__ __forceinline__ void gemm_body(const __half* __restrict__ A,
                                          const __half* __restrict__ B,
                                          void* __restrict__ Cv, float scale) {
    extern __shared__ __half gsm[];
    const int K = DM, N = DM;
    const int tid = threadIdx.x, lane = tid & 31, wid = tid >> 5;
    const int g = lane >> 2, t4 = lane & 3;
    const int wm = wid >> 2, wn = wid & 3;
    const int row0 = blockIdx.y * 128, col0 = blockIdx.x * 128;
    const int arow = (lane & 7) + ((lane >> 3) & 1) * 8;
    const int acol = (lane >> 4) * 8;

    float acc[4][4][4];
#pragma unroll
    for (int m = 0; m < 4; m++)
#pragma unroll
        for (int n = 0; n < 4; n++)
#pragma unroll
            for (int i = 0; i < 4; i++) acc[m][n][i] = 0.f;

    auto issue = [&](int kt) {
        int buf = kt % 3;
        __half* As = gsm + buf * GA_SZ;
        __half* Bs = gsm + 3 * GA_SZ + buf * GB_SZ;
#pragma unroll
        for (int i = 0; i < 2; i++) {
            int f = tid + i * 256, r = f >> 2, c8 = (f & 3) * 8;
            cpa16(As + r * GA_ST + c8,
                  A + (size_t)(row0 + r) * K + kt * 32 + c8);
        }
#pragma unroll
        for (int i = 0; i < 2; i++) {
            int f = tid + i * 256, r = f >> 4, c8 = (f & 15) * 8;
            cpa16(Bs + r * GB_ST + c8,
                  B + (size_t)(kt * 32 + r) * N + col0 + c8);
        }
    };

    const int nk = K / 32;
    issue(0);
    CPCOMMIT;
    issue(1);
    CPCOMMIT;

    for (int kt = 0; kt < nk; kt++) {
        CPWAIT(1);
        __syncthreads();
        int buf = kt % 3;
        __half* As = gsm + buf * GA_SZ;
        __half* Bs = gsm + 3 * GA_SZ + buf * GB_SZ;
#pragma unroll
        for (int kk = 0; kk < 2; kk++) {
            unsigned af[4][4];
#pragma unroll
            for (int m = 0; m < 4; m++)
                ldsm4(af[m][0], af[m][1], af[m][2], af[m][3],
                      s2u(As + (wm * 64 + m * 16 + arow) * GA_ST + kk * 16 +
                          acol));
            unsigned bf[4][2];
#pragma unroll
            for (int np = 0; np < 2; np++) {
                unsigned r0, r1, r2, r3;
                ldsm4t(r0, r1, r2, r3,
                       s2u(Bs + (kk * 16 + arow) * GB_ST + wn * 32 + np * 16 +
                           acol));
                bf[np * 2][0] = r0;
                bf[np * 2][1] = r1;
                bf[np * 2 + 1][0] = r2;
                bf[np * 2 + 1][1] = r3;
            }
#pragma unroll
            for (int m = 0; m < 4; m++)
#pragma unroll
                for (int n = 0; n < 4; n++)
                    mma16(acc[m][n], af[m][0], af[m][1], af[m][2], af[m][3],
                          bf[n][0], bf[n][1]);
        }
        if (kt + 2 < nk) issue(kt + 2);
        CPCOMMIT;
    }

#pragma unroll
    for (int m = 0; m < 4; m++) {
#pragma unroll
        for (int n = 0; n < 4; n++) {
            int row = row0 + wm * 64 + m * 16 + g;
            int col = col0 + wn * 32 + n * 8 + 2 * t4;
            if (HSPLIT) {
                __half* C = (__half*)Cv;
                int b = row >> 11, l = row & (LL - 1);
                int h = col >> 6, d = col & 63;
                size_t idx = ((size_t)(b * NH + h) * LL + l) * 64 + d;
                *(__half2*)&C[idx] = __floats2half2_rn(acc[m][n][0] * scale,
                                                       acc[m][n][1] * scale);
                *(__half2*)&C[idx + (size_t)8 * 64] = __floats2half2_rn(
                    acc[m][n][2] * scale, acc[m][n][3] * scale);
            } else {
                float* C = (float*)Cv;
                size_t idx = (size_t)row * N + col;
                float2 v0 = {acc[m][n][0] * scale, acc[m][n][1] * scale};
                float2 v1 = {acc[m][n][2] * scale, acc[m][n][3] * scale};
                *(float2*)&C[idx] = v0;
                *(float2*)&C[idx + (size_t)8 * N] = v1;
            }
        }
    }
}

// Q/K/V projections in ONE launch: grid.z picks operands.
struct QKVArgs {
    const __half* A[3];
    const __half* B[3];
    __half* C[3];
    float scale[3];
};
__global__ __launch_bounds__(256) void gemm_qkv(QKVArgs a) {
    int z = blockIdx.z;
    gemm_body<true>(a.A[z], a.B[z], a.C[z], a.scale[z]);
}

__global__ __launch_bounds__(256) void gemm_out(const __half* __restrict__ A,
                                                const __half* __restrict__ B,
                                                float* __restrict__ C) {
    gemm_body<false>(A, B, C, 1.0f);
}

// ---------------------------------------------------------------------------
// Kernel 3: flash attention. CTA = (128 q rows, 1 head).
// P in registers; l via ones-column MMA (constant B fragment);
// masking by plain add (exp underflow == reference's replace semantics);
// BM gmem->regs in one reused 16-reg batch; K/V double-buffered cp.async.
// ---------------------------------------------------------------------------
#define KV_SZ (64 * 72)
#define ATTN_SMEM ((128 * 72 + 4 * KV_SZ) * 2)  // 55296 B

__global__ __launch_bounds__(256, 2) void attn_kernel() {
    extern __shared__ __half smh[];
    __half* Qs = smh;                  // [128][72]
    __half* Ksb = smh + 128 * 72;      // [2][64][72]
    __half* Vsb = Ksb + 2 * KV_SZ;     // [2][64][72]

    const int b = blockIdx.z, h = blockIdx.y, qt = blockIdx.x;
    const int tid = threadIdx.x, lane = tid & 31, wid = tid >> 5;
    const int g = lane >> 2, t4 = lane & 3;
    const int wrow = wid * 16;
    const int arow = (lane & 7) + ((lane >> 3) & 1) * 8;  // A-style / trans-B
    const int acol = (lane >> 4) * 8;
    const int brow = (lane & 7) + (lane >> 4) * 8;        // non-trans B (S)
    const int bcol = ((lane >> 3) & 1) * 8;
    // constant B fragment: ones in column n=0 -> row-sum of P via the MMA
    const unsigned bb = (g == 0) ? 0x3C003C00u : 0u;

    const __half* Qp = g_Qh + ((size_t)(b * NH + h) * LL + qt * TQ) * DKV;
    const __half* Kp = g_Kh + (size_t)(b * NH + h) * LL * DKV;
    const __half* Vp = g_Vh + (size_t)(b * NH + h) * LL * DKV;
    const float* BMp = g_BM + ((size_t)b * LL + qt * TQ) * LL;

    auto issue_kv = [&](int kt, int buf) {
#pragma unroll
        for (int i = 0; i < 2; i++) {
            int f = tid + i * 256, r = f >> 3, c8 = (f & 7) * 8;
            cpa16(Ksb + buf * KV_SZ + r * 72 + c8,
                  Kp + (size_t)(kt * TK + r) * 64 + c8);
            cpa16(Vsb + buf * KV_SZ + r * 72 + c8,
                  Vp + (size_t)(kt * TK + r) * 64 + c8);
        }
    };

    // Q tile (once) + first K/V tile, one cp.async group
#pragma unroll
    for (int i = 0; i < 4; i++) {
        int f = tid + i * 256, r = f >> 3, c8 = (f & 7) * 8;
        cpa16(Qs + r * 72 + c8, Qp + (size_t)r * 64 + c8);
    }
    issue_kv(0, 0);
    CPCOMMIT;

    float m_i[2] = {-1e30f, -1e30f};
    float lacc[4] = {0.f, 0.f, 0.f, 0.f};
    float oacc[8][4];
#pragma unroll
    for (int nf = 0; nf < 8; nf++)
#pragma unroll
        for (int i = 0; i < 4; i++) oacc[nf][i] = 0.f;

    for (int kt = 0; kt < NT; kt++) {
        int cur = kt & 1;
        CPWAIT(0);
        __syncthreads();
        if (kt + 1 < NT) {
            issue_kv(kt + 1, cur ^ 1);
            CPCOMMIT;
        }
        __half* Ks = Ksb + cur * KV_SZ;
        __half* Vs = Vsb + cur * KV_SZ;

        // BM batch 0 (nf 0..3): gmem -> regs, hidden under the S-mma
        float2 bm[8];
#pragma unroll
        for (int nf = 0; nf < 4; nf++)
#pragma unroll
            for (int rr = 0; rr < 2; rr++)
                bm[nf * 2 + rr] = *(const float2*)(
                    BMp + (size_t)(wrow + g + rr * 8) * LL + kt * TK + nf * 8 +
                    2 * t4);

        // S = Q @ K^T
        float sacc[8][4];
#pragma unroll
        for (int nf = 0; nf < 8; nf++)
#pragma unroll
            for (int i = 0; i < 4; i++) sacc[nf][i] = 0.f;
#pragma unroll
        for (int kk = 0; kk < 4; kk++) {
            unsigned a0, a1, a2, a3;
            ldsm4(a0, a1, a2, a3,
                  s2u(Qs + (wrow + arow) * 72 + kk * 16 + acol));
#pragma unroll
            for (int np = 0; np < 4; np++) {
                unsigned r0, r1, r2, r3;
                ldsm4(r0, r1, r2, r3,
                      s2u(Ks + (np * 16 + brow) * 72 + kk * 16 + bcol));
                mma16(sacc[np * 2], a0, a1, a2, a3, r0, r1);
                mma16(sacc[np * 2 + 1], a0, a1, a2, a3, r2, r3);
            }
        }

        // bias/mask: plain add (masked -> s-10000 -> exp underflows to 0,
        // matching the reference's replace-then-softmax exactly)
        float mloc[2] = {-1e30f, -1e30f};
#pragma unroll
        for (int nf = 0; nf < 4; nf++) {
#pragma unroll
            for (int rr = 0; rr < 2; rr++) {
                float s0 = sacc[nf][rr * 2 + 0] + bm[nf * 2 + rr].x;
                float s1 = sacc[nf][rr * 2 + 1] + bm[nf * 2 + rr].y;
                sacc[nf][rr * 2 + 0] = s0;
                sacc[nf][rr * 2 + 1] = s1;
                mloc[rr] = fmaxf(mloc[rr], fmaxf(s0, s1));
            }
        }
        // BM batch 1 (nf 4..7) reuses the same registers
#pragma unroll
        for (int nf = 0; nf < 4; nf++)
#pragma unroll
            for (int rr = 0; rr < 2; rr++)
                bm[nf * 2 + rr] = *(const float2*)(
                    BMp + (size_t)(wrow + g + rr * 8) * LL + kt * TK +
                    (nf + 4) * 8 + 2 * t4);
#pragma unroll
        for (int nf = 4; nf < 8; nf++) {
#pragma unroll
            for (int rr = 0; rr < 2; rr++) {
                float s0 = sacc[nf][rr * 2 + 0] + bm[(nf - 4) * 2 + rr].x;
                float s1 = sacc[nf][rr * 2 + 1] + bm[(nf - 4) * 2 + rr].y;
                sacc[nf][rr * 2 + 0] = s0;
                sacc[nf][rr * 2 + 1] = s1;
                mloc[rr] = fmaxf(mloc[rr], fmaxf(s0, s1));
            }
        }
#pragma unroll
        for (int rr = 0; rr < 2; rr++) {
            mloc[rr] = fmaxf(mloc[rr], __shfl_xor_sync(0xffffffffu, mloc[rr], 1));
            mloc[rr] = fmaxf(mloc[rr], __shfl_xor_sync(0xffffffffu, mloc[rr], 2));
        }
        float alpha[2], nmL[2];
#pragma unroll
        for (int rr = 0; rr < 2; rr++) {
            float mn = fmaxf(m_i[rr], mloc[rr]);
            alpha[rr] = ex2f((m_i[rr] - mn) * L2E);
            m_i[rr] = mn;
            nmL[rr] = -mn * L2E;
        }
        // P = exp2(s*log2e - m*log2e), packed straight to half2 A-fragments
        unsigned pk[16];
#pragma unroll
        for (int nf = 0; nf < 8; nf++) {
#pragma unroll
            for (int rr = 0; rr < 2; rr++) {
                float p0 = ex2f(fmaf(sacc[nf][rr * 2 + 0], L2E, nmL[rr]));
                float p1 = ex2f(fmaf(sacc[nf][rr * 2 + 1], L2E, nmL[rr]));
                pk[nf * 2 + rr] = pack2(p0, p1);
            }
        }
        // rescale running O and l by alpha
#pragma unroll
        for (int nf = 0; nf < 8; nf++) {
            oacc[nf][0] *= alpha[0];
            oacc[nf][1] *= alpha[0];
            oacc[nf][2] *= alpha[1];
            oacc[nf][3] *= alpha[1];
        }
        lacc[0] *= alpha[0];
        lacc[1] *= alpha[0];
        lacc[2] *= alpha[1];
        lacc[3] *= alpha[1];

        // O += P @ V ; l += P @ ones (constant B fragment, col 0)
#pragma unroll
        for (int kk = 0; kk < 4; kk++) {
            unsigned a0 = pk[4 * kk + 0], a1 = pk[4 * kk + 1];
            unsigned a2 = pk[4 * kk + 2], a3 = pk[4 * kk + 3];
            mma16(lacc, a0, a1, a2, a3, bb, bb);
#pragma unroll
            for (int np = 0; np < 4; np++) {
                unsigned r0, r1, r2, r3;
                ldsm4t(r0, r1, r2, r3,
                       s2u(Vs + (kk * 16 + arow) * 72 + np * 16 + acol));
                mma16(oacc[np * 2], a0, a1, a2, a3, r0, r1);
                mma16(oacc[np * 2 + 1], a0, a1, a2, a3, r2, r3);
            }
        }
    }

    // l lives in column 0 of the lacc fragment: threads t4==0, c0 (row g)
    // and c2 (row g+8). Broadcast within each quad.
    float l0 = __shfl_sync(0xffffffffu, lacc[0], lane & ~3);
    float l1 = __shfl_sync(0xffffffffu, lacc[2], lane & ~3);
    float inv0 = 1.f / l0, inv1 = 1.f / l1;
#pragma unroll
    for (int nf = 0; nf < 8; nf++) {
        int col = nf * 8 + 2 * t4;
        int row = qt * TQ + wrow + g;
        size_t idx = ((size_t)b * LL + row) * DM + h * DKV + col;
        *(__half2*)&g_O[idx] =
            __floats2half2_rn(oacc[nf][0] * inv0, oacc[nf][1] * inv0);
        *(__half2*)&g_O[idx + (size_t)8 * DM] =
            __floats2half2_rn(oacc[nf][2] * inv1, oacc[nf][3] * inv1);
    }
}

// ---------------------------------------------------------------------------
// Launch
// ---------------------------------------------------------------------------
extern "C" void kernel_launch(void* const* d_in, const int* in_sizes, int n_in,
                              void* d_out, int out_size) {
    float* out = (float*)d_out;

    __half *hq, *hk, *hv, *hw, *Qh, *Kh, *Vh, *O;
    float* BM;
    cudaGetSymbolAddress((void**)&hq, g_hq);
    cudaGetSymbolAddress((void**)&hk, g_hk);
    cudaGetSymbolAddress((void**)&hv, g_hv);
    cudaGetSymbolAddress((void**)&hw, g_hw);
    cudaGetSymbolAddress((void**)&Qh, g_Qh);
    cudaGetSymbolAddress((void**)&Kh, g_Kh);
    cudaGetSymbolAddress((void**)&Vh, g_Vh);
    cudaGetSymbolAddress((void**)&BM, g_BM);
    cudaGetSymbolAddress((void**)&O, g_O);
    size_t WSZ = (size_t)DM * DM;

    cudaFuncSetAttribute(attn_kernel,
                         cudaFuncAttributeMaxDynamicSharedMemorySize,
                         ATTN_SMEM);
    cudaFuncSetAttribute(gemm_qkv,
                         cudaFuncAttributeMaxDynamicSharedMemorySize,
                         GEMM_SMEM);
    cudaFuncSetAttribute(gemm_out,
                         cudaFuncAttributeMaxDynamicSharedMemorySize,
                         GEMM_SMEM);

    // 0. merged prep: fp32->fp16 converts + mask/bias fusion
    PrepArgs pa;
    pa.s[0] = (const float4*)d_in[0];
    pa.s[1] = (const float4*)d_in[1];
    pa.s[2] = (const float4*)d_in[2];
    pa.s[3] = (const float4*)d_in[5];
    pa.s[4] = (const float4*)d_in[6];
    pa.s[5] = (const float4*)d_in[7];
    pa.s[6] = (const float4*)d_in[8];
    pa.d[0] = (uint2*)hq;
    pa.d[1] = (uint2*)hk;
    pa.d[2] = (uint2*)hv;
    pa.d[3] = (uint2*)(hw + 0 * WSZ);
    pa.d[4] = (uint2*)(hw + 1 * WSZ);
    pa.d[5] = (uint2*)(hw + 2 * WSZ);
    pa.d[6] = (uint2*)(hw + 3 * WSZ);
    pa.mask = (const int4*)d_in[3];
    pa.bias = (const float4*)d_in[4];
    pa.bm = (float4*)BM;
    prep_kernel<<<4096 + 8192, 256>>>(pa);

    // 1. Q/K/V projections in one launch (Q pre-scaled by 1/8)
    QKVArgs qa;
    qa.A[0] = hq;
    qa.A[1] = hk;
    qa.A[2] = hv;
    qa.B[0] = hw + 0 * WSZ;
    qa.B[1] = hw + 1 * WSZ;
    qa.B[2] = hw + 2 * WSZ;
    qa.C[0] = Qh;
    qa.C[1] = Kh;
    qa.C[2] = Vh;
    qa.scale[0] = 0.125f;
    qa.scale[1] = 1.0f;
    qa.scale[2] = 1.0f;
    gemm_qkv<<<dim3(DM / 128, (BB * LL) / 128, 3), 256, GEMM_SMEM>>>(qa);

    // 2. attention
    attn_kernel<<<dim3(LL / TQ, NH, BB), 256, ATTN_SMEM>>>();

    // 3. output projection (half in, fp32 out)
    gemm_out<<<dim3(DM / 128, (BB * LL) / 128), 256, GEMM_SMEM>>>(
        O, hw + 3 * WSZ, out);
}